// round 10
// baseline (speedup 1.0000x reference)
#include <cuda_runtime.h>
#include <math.h>

#define DIM   1024
#define NCAND 16384
#define SSZ   512
#define MSZ   4096
#define LSZ   8192
#define KPROM 128
#define LPB   128
#define NB    148   // fused-kernel grid (<= SM count: co-residency guaranteed)

// ---------------- device scratch (no allocations allowed) ----------------
__device__ float g_norms[NCAND];
__device__ int   g_topidx[KPROM];
__device__ float g_part[LPB * DIM];
__device__ float g_lmean[DIM];
__device__ float g_q[DIM];
__device__ float g_u[DIM];
__device__ float g_logits[SSZ];
__device__ int   g_best_s;
__device__ float g_cand[DIM];
__device__ float g_cnsq;
__device__ float g_mdot[MSZ];
__device__ float g_mnsq[MSZ];
__device__ float g_minv[MSZ];
__device__ int   g_msi;
__device__ float g_simcand;
__device__ unsigned long long g_pairmax;
__device__ float g_mumean, g_lumean;
__device__ int   g_li, g_lj, g_isfull, g_mi;
__device__ int   g_mi8[MSZ * 256];
__device__ float g_sfac[MSZ];
__device__ float g_tmax64[64 * 64];
__device__ unsigned g_qmax;
__device__ int g_bcnt = 0;
__device__ int g_bgen = 0;

// ---------------- helpers ----------------
__device__ __forceinline__ void gridbar(int nblocks) {
    __syncthreads();
    if (threadIdx.x == 0) {
        volatile int* vgen = &g_bgen;
        int my = *vgen;
        __threadfence();
        int t = atomicAdd(&g_bcnt, 1);
        if (t == nblocks - 1) {
            g_bcnt = 0;
            __threadfence();
            atomicAdd(&g_bgen, 1);
        } else {
            while (*vgen == my) { }
        }
        __threadfence();
    }
    __syncthreads();
}

__device__ __forceinline__ float blockReduceSum(float v) {
    __shared__ float sh[32];
    int lane = threadIdx.x & 31, wid = threadIdx.x >> 5;
    __syncthreads();
#pragma unroll
    for (int o = 16; o; o >>= 1) v += __shfl_down_sync(0xFFFFFFFFu, v, o);
    if (lane == 0) sh[wid] = v;
    __syncthreads();
    int nw = (blockDim.x + 31) >> 5;
    v = (threadIdx.x < nw) ? sh[threadIdx.x] : 0.f;
    if (wid == 0) {
#pragma unroll
        for (int o = 16; o; o >>= 1) v += __shfl_down_sync(0xFFFFFFFFu, v, o);
    }
    return v;  // valid in tid 0
}

__device__ __forceinline__ float blockReduceMax(float v) {
    __shared__ float shm[32];
    int lane = threadIdx.x & 31, wid = threadIdx.x >> 5;
    __syncthreads();
#pragma unroll
    for (int o = 16; o; o >>= 1) v = fmaxf(v, __shfl_down_sync(0xFFFFFFFFu, v, o));
    if (lane == 0) shm[wid] = v;
    __syncthreads();
    int nw = (blockDim.x + 31) >> 5;
    v = (threadIdx.x < nw) ? shm[threadIdx.x] : -1e30f;
    if (wid == 0) {
#pragma unroll
        for (int o = 16; o; o >>= 1) v = fmaxf(v, __shfl_down_sync(0xFFFFFFFFu, v, o));
    }
    return v;  // valid in tid 0
}

__device__ __forceinline__ void blockArgBest(float v, int idx, int maxMode,
                                             float* outv, int* outi) {
    __shared__ float sv[1024];
    __shared__ int   si[1024];
    __syncthreads();
    sv[threadIdx.x] = v; si[threadIdx.x] = idx;
    __syncthreads();
    for (int s = blockDim.x >> 1; s; s >>= 1) {
        if ((int)threadIdx.x < s) {
            float v2 = sv[threadIdx.x + s]; int i2 = si[threadIdx.x + s];
            bool better = maxMode
                ? (v2 > sv[threadIdx.x] || (v2 == sv[threadIdx.x] && i2 < si[threadIdx.x]))
                : (v2 < sv[threadIdx.x] || (v2 == sv[threadIdx.x] && i2 < si[threadIdx.x]));
            if (better) { sv[threadIdx.x] = v2; si[threadIdx.x] = i2; }
        }
        __syncthreads();
    }
    if (threadIdx.x == 0) { if (outv) *outv = sv[0]; *outi = si[0]; }
    __syncthreads();
}

__device__ __forceinline__ unsigned ordf(float f) {
    unsigned u = __float_as_uint(f);
    return (u & 0x80000000u) ? ~u : (u | 0x80000000u);
}
__device__ __forceinline__ float iordf(unsigned u) {
    unsigned b = (u & 0x80000000u) ? (u & 0x7FFFFFFFu) : ~u;
    return __uint_as_float(b);
}

__device__ __forceinline__ float warpRowDot(const float4* __restrict__ a4,
                                            const float4* __restrict__ b4,
                                            int lane) {
    float s = 0.f;
#pragma unroll
    for (int k = 0; k < 8; ++k) {
        float4 a = a4[lane + k * 32];
        float4 b = b4[lane + k * 32];
        s += a.x*b.x + a.y*b.y + a.z*b.z + a.w*b.w;
    }
#pragma unroll
    for (int o = 16; o; o >>= 1) s += __shfl_down_sync(0xFFFFFFFFu, s, o);
    return s;  // valid in lane 0
}

// ===== Kernel A: init + mnq(warp/row) + rownorms(warp/row) + lpart =====
#define KA_MNQB   512
#define KA_RNB    2048
__global__ void kA(const float* __restrict__ m, const float* __restrict__ tok,
                   const float* __restrict__ l) {
    int b = blockIdx.x, t = threadIdx.x;
    int lane = t & 31, w = t >> 5;
    if (b < KA_MNQB) {
        if (b == 0 && t == 0) { g_pairmax = 0ULL; g_qmax = 0u; }
        int row = b * 8 + w;
        const float4* p = (const float4*)(m + (size_t)row * DIM);
        float4 va[8];
        float nsq = 0.f, mab = 0.f;
#pragma unroll
        for (int k = 0; k < 8; ++k) {
            float4 v = p[lane + k * 32];
            va[k] = v;
            nsq += v.x*v.x + v.y*v.y + v.z*v.z + v.w*v.w;
            mab = fmaxf(mab, fmaxf(fmaxf(fabsf(v.x), fabsf(v.y)),
                                   fmaxf(fabsf(v.z), fabsf(v.w))));
        }
#pragma unroll
        for (int o = 16; o; o >>= 1) {
            nsq += __shfl_down_sync(0xFFFFFFFFu, nsq, o);
            mab = fmaxf(mab, __shfl_down_sync(0xFFFFFFFFu, mab, o));
        }
        float is;
        if (lane == 0) {
            g_mnsq[row] = nsq;
            float inv = 1.f / fmaxf(sqrtf(nsq), 1e-12f);
            g_minv[row] = inv;
            float scale = (mab > 0.f) ? mab / 127.f : 1.f;
            g_sfac[row] = scale * inv;
            is = (mab > 0.f) ? 127.f / mab : 0.f;
        }
        is = __shfl_sync(0xFFFFFFFFu, is, 0);
#pragma unroll
        for (int k = 0; k < 8; ++k) {
            float4 v = va[k];
            int q0 = max(-127, min(127, __float2int_rn(v.x * is)));
            int q1 = max(-127, min(127, __float2int_rn(v.y * is)));
            int q2 = max(-127, min(127, __float2int_rn(v.z * is)));
            int q3 = max(-127, min(127, __float2int_rn(v.w * is)));
            g_mi8[row * 256 + lane + k * 32] =
                (q0 & 0xFF) | ((q1 & 0xFF) << 8) | ((q2 & 0xFF) << 16) | ((q3 & 0xFF) << 24);
        }
    } else if (b < KA_MNQB + KA_RNB) {
        int row = (b - KA_MNQB) * 8 + w;
        const float4* p = (const float4*)(tok + (size_t)row * DIM);
        float s = 0.f;
#pragma unroll
        for (int k = 0; k < 8; ++k) {
            float4 v = p[lane + k * 32];
            s += v.x*v.x + v.y*v.y + v.z*v.z + v.w*v.w;
        }
#pragma unroll
        for (int o = 16; o; o >>= 1) s += __shfl_down_sync(0xFFFFFFFFu, s, o);
        if (lane == 0) g_norms[row] = s;
    } else {
        int b2 = b - KA_MNQB - KA_RNB;
        float acc[4] = {0.f, 0.f, 0.f, 0.f};
        int r0 = b2 * (LSZ / LPB);
        for (int r = 0; r < LSZ / LPB; ++r) {
            const float* row = l + (size_t)(r0 + r) * DIM;
#pragma unroll
            for (int k = 0; k < 4; ++k) acc[k] += row[t + k * 256];
        }
#pragma unroll
        for (int k = 0; k < 4; ++k) g_part[b2 * DIM + t + k * 256] = acc[k];
    }
}

// ================= Kernel C: fast top-128 =================
__global__ __launch_bounds__(1024) void k_topk() {
    int tid = threadIdx.x, lane = tid & 31, warp = tid >> 5;
    unsigned long long key[16];
#pragma unroll
    for (int i = 0; i < 16; ++i) {
        int idx = tid + i * 1024;
        key[i] = ((unsigned long long)ordf(g_norms[idx]) << 32) |
                 (unsigned long long)(0xFFFFFFFFu - (unsigned)idx);
    }
    unsigned long long lmax = 0ULL;
#pragma unroll
    for (int i = 0; i < 16; ++i) if (key[i] > lmax) lmax = key[i];

    __shared__ unsigned long long wkey[32];
    __shared__ unsigned long long winner;
    for (int it = 0; it < KPROM; ++it) {
        unsigned long long k = lmax;
#pragma unroll
        for (int o = 16; o; o >>= 1) {
            unsigned long long o2 = __shfl_down_sync(0xFFFFFFFFu, k, o);
            if (o2 > k) k = o2;
        }
        if (lane == 0) wkey[warp] = k;
        __syncthreads();
        if (warp == 0) {
            unsigned long long k2 = wkey[lane];
#pragma unroll
            for (int o = 16; o; o >>= 1) {
                unsigned long long o2 = __shfl_down_sync(0xFFFFFFFFu, k2, o);
                if (o2 > k2) k2 = o2;
            }
            if (lane == 0) {
                winner = k2;
                g_topidx[it] = (int)(0xFFFFFFFFu - (unsigned)(k2 & 0xFFFFFFFFu));
            }
        }
        __syncthreads();
        unsigned long long w = winner;
        if (lmax == w) {
            unsigned long long nm = 0ULL;
#pragma unroll
            for (int i = 0; i < 16; ++i) {
                if (key[i] == w) key[i] = 0ULL;
                if (key[i] > nm) nm = key[i];
            }
            lmax = nm;
        }
    }
}

// ==== Kernel D: fused serial chain, 1024 thr/block, warp-per-row dots ====
__global__ __launch_bounds__(1024) void kD(const float* __restrict__ tok,
                                           const float* __restrict__ s_in,
                                           const int* __restrict__ sptr,
                                           const float* __restrict__ wq,
                                           const float* __restrict__ bq,
                                           const float* __restrict__ wk,
                                           const float* __restrict__ m,
                                           float* __restrict__ out_s) {
    int b = blockIdx.x, t = threadIdx.x;
    int lane = t & 31, w = t >> 5;
    int gw = b * 32 + w;

    // p0: build_s + lsum (block 0)
    {
        int sp = *sptr;
        for (int idx = b * 1024 + t; idx < SSZ * 256; idx += NB * 1024) {
            int r = idx >> 8, c = idx & 255;
            int d = ((r - sp) % SSZ + SSZ) % SSZ;
            const float4* src = (d < KPROM)
                ? (const float4*)(tok + (size_t)g_topidx[d] * DIM)
                : (const float4*)(s_in + (size_t)r * DIM);
            ((float4*)(out_s + (size_t)r * DIM))[c] = src[c];
        }
        if (b == 0) {
            float s = 0.f;
            for (int p = 0; p < LPB; ++p) s += g_part[p * DIM + t];
            g_lmean[t] = s * (1.f / (float)LSZ);
        }
    }
    gridbar(NB);

    // p1: q[j]
    if (gw < DIM) {
        float s = warpRowDot((const float4*)(wq + (size_t)gw * DIM),
                             (const float4*)g_lmean, lane);
        if (lane == 0) g_q[gw] = s + bq[gw];
    }
    gridbar(NB);

    // p2: u partials
    if (b < 128) {
        float acc = 0.f;
#pragma unroll
        for (int jj = 0; jj < 8; ++jj) {
            int j = b * 8 + jj;
            acc += wk[(size_t)j * DIM + t] * g_q[j];
        }
        g_part[b * DIM + t] = acc;
    }
    gridbar(NB);

    // p3: usum
    if (b == 0) {
        float s = 0.f;
        for (int p = 0; p < 128; ++p) s += g_part[p * DIM + t];
        g_u[t] = s;
    }
    gridbar(NB);

    // p4: logits
    if (gw < SSZ) {
        float s = warpRowDot((const float4*)(out_s + (size_t)gw * DIM),
                             (const float4*)g_u, lane);
        if (lane == 0) g_logits[gw] = s;
    }
    gridbar(NB);

    // p5: pick
    if (b == 0) {
        float bv = -1e30f; int bi = 0x7FFFFFFF;
        if (t < SSZ) { bv = g_logits[t]; bi = t; }
        blockArgBest(bv, bi, 1, nullptr, &g_best_s);
        int bs = g_best_s;
        float loc = 0.f;
        if (t < 256) {
            float4 v4 = ((const float4*)(out_s + (size_t)bs * DIM))[t];
            ((float4*)g_cand)[t] = v4;
            loc = v4.x*v4.x + v4.y*v4.y + v4.z*v4.z + v4.w*v4.w;
        }
        float tot = blockReduceSum(loc);
        if (t == 0) g_cnsq = tot;
    }
    gridbar(NB);

    // p6: mdots
    if (gw < MSZ) {
        float s = warpRowDot((const float4*)(m + (size_t)gw * DIM),
                             (const float4*)g_cand, lane);
        if (lane == 0) g_mdot[gw] = s;
    }
    gridbar(NB);

    // p7: mstats
    if (b == 0) {
        float cinv = 1.f / fmaxf(sqrtf(g_cnsq), 1e-12f);
        float bv = -1e30f; int bi = 0x7FFFFFFF;
        for (int i = t; i < MSZ; i += 1024) {
            float s = g_mdot[i] * g_minv[i] * cinv;
            if (s > bv) { bv = s; bi = i; }
        }
        blockArgBest(bv, bi, 1, &g_simcand, &g_msi);
    }
}

// ====== Kernel B: int8 DP4A pair-similarity, 64x64 tiles, 4 CTA/SM ======
// 2080 blocks over 64x64 lower-tri tile grid. Thread tile 4x4, 16 accs.
// smem 18.4KB/block, ~56 regs => 4 CTAs/SM = 8 warps/SMSP (2x latency hiding).
#define LDR 36
__global__ __launch_bounds__(256, 4) void k_pairmax_i8() {
    __shared__ int As[64 * LDR];
    __shared__ int Bs[64 * LDR];
    __shared__ float sfA[64], sfB[64];

    int b = blockIdx.x;  // 2080 = 64*65/2
    int bi = (int)((sqrtf(8.f * b + 1.f) - 1.f) * 0.5f);
    while ((bi + 1) * (bi + 2) / 2 <= b) ++bi;
    while (bi * (bi + 1) / 2 > b) --bi;
    int bj = b - bi * (bi + 1) / 2;
    int rowA = bi * 64, rowB = bj * 64;

    int tid = threadIdx.x;
    int tx = tid & 15, ty = tid >> 4;

    if (tid < 64)       sfA[tid] = g_sfac[rowA + tid];
    else if (tid < 128) sfB[tid - 64] = g_sfac[rowB + tid - 64];

    int acc[4][4];
#pragma unroll
    for (int i = 0; i < 4; ++i)
#pragma unroll
        for (int j = 0; j < 4; ++j) acc[i][j] = 0;

    int ldrow = tid >> 2, ldoff = (tid & 3) * 8;  // 8 ints per thread per tile

    for (int c = 0; c < 8; ++c) {  // K chunks of 128 int8 (32 ints)
        __syncthreads();
        {
            const int* gA = &g_mi8[(size_t)(rowA + ldrow) * 256 + c * 32 + ldoff];
            const int* gB = &g_mi8[(size_t)(rowB + ldrow) * 256 + c * 32 + ldoff];
            int* sA = &As[ldrow * LDR + ldoff];
            int* sB = &Bs[ldrow * LDR + ldoff];
            *(int4*)(sA)     = *(const int4*)(gA);
            *(int4*)(sA + 4) = *(const int4*)(gA + 4);
            *(int4*)(sB)     = *(const int4*)(gB);
            *(int4*)(sB + 4) = *(const int4*)(gB + 4);
        }
        __syncthreads();
        const int* arow = &As[(ty * 4) * LDR];
        const int* brow = &Bs[tx * LDR];
#pragma unroll
        for (int kq = 0; kq < 8; ++kq) {
            int4 b4[4];
#pragma unroll
            for (int j = 0; j < 4; ++j)
                b4[j] = *(const int4*)&brow[(j * 16) * LDR + kq * 4];
#pragma unroll
            for (int i = 0; i < 4; ++i) {
                int4 a4 = *(const int4*)&arow[i * LDR + kq * 4];
#pragma unroll
                for (int j = 0; j < 4; ++j) {
                    int s = __dp4a(a4.x, b4[j].x, acc[i][j]);
                    s = __dp4a(a4.y, b4[j].y, s);
                    s = __dp4a(a4.z, b4[j].z, s);
                    acc[i][j] = __dp4a(a4.w, b4[j].w, s);
                }
            }
        }
    }

    // epilogue: tile max of int8 sims over strict-lower pairs
    float mx = -1e30f;
#pragma unroll
    for (int i = 0; i < 4; ++i) {
        int ri = ty * 4 + i;
        int gi = rowA + ri;
        float fi = sfA[ri];
#pragma unroll
        for (int j = 0; j < 4; ++j) {
            int cj = tx + 16 * j;
            int gj = rowB + cj;
            if (gi > gj) mx = fmaxf(mx, (float)acc[i][j] * fi * sfB[cj]);
        }
    }
    float tmax = blockReduceMax(mx);
    if (tid == 0) {
        g_tmax64[bi * 64 + bj] = tmax;
        atomicMax(&g_qmax, ordf(tmax));
    }
}

// ==== Kernel E: exact fp32 recompute of candidate tiles ====
#define TS 64
#define KT 16
__global__ __launch_bounds__(256) void k_pairmax_exact(const float* __restrict__ M) {
    int b = blockIdx.x;
    int bi = (int)((sqrtf(8.f * b + 1.f) - 1.f) * 0.5f);
    while ((bi + 1) * (bi + 2) / 2 <= b) ++bi;
    while (bi * (bi + 1) / 2 > b) --bi;
    int bj = b - bi * (bi + 1) / 2;

    float tmax = g_tmax64[bi * 64 + bj];
    float gmax = iordf(g_qmax);
    if (tmax < gmax - 0.025f) return;  // int8 sim error <= 0.011; rigorous margin

    __shared__ float As[TS][KT + 1];
    __shared__ float Bs[TS][KT + 1];
    int tid = threadIdx.x;
    int tx = tid & 15, ty = tid >> 4;
    float acc[4][4];
#pragma unroll
    for (int i = 0; i < 4; ++i)
#pragma unroll
        for (int j = 0; j < 4; ++j) acc[i][j] = 0.f;

    int rowA = bi * TS, rowB = bj * TS;
    int lr = tid >> 2;
    int lc = (tid & 3) * 4;

    for (int k0 = 0; k0 < DIM; k0 += KT) {
        float4 a4 = *(const float4*)&M[(size_t)(rowA + lr) * DIM + k0 + lc];
        float4 b4 = *(const float4*)&M[(size_t)(rowB + lr) * DIM + k0 + lc];
        As[lr][lc] = a4.x; As[lr][lc+1] = a4.y; As[lr][lc+2] = a4.z; As[lr][lc+3] = a4.w;
        Bs[lr][lc] = b4.x; Bs[lr][lc+1] = b4.y; Bs[lr][lc+2] = b4.z; Bs[lr][lc+3] = b4.w;
        __syncthreads();
#pragma unroll
        for (int kk = 0; kk < KT; ++kk) {
            float a[4], bb[4];
#pragma unroll
            for (int i = 0; i < 4; ++i) a[i] = As[ty * 4 + i][kk];
#pragma unroll
            for (int j = 0; j < 4; ++j) bb[j] = Bs[tx * 4 + j][kk];
#pragma unroll
            for (int i = 0; i < 4; ++i)
#pragma unroll
                for (int j = 0; j < 4; ++j) acc[i][j] += a[i] * bb[j];
        }
        __syncthreads();
    }

    unsigned long long best = 0ULL;
#pragma unroll
    for (int i = 0; i < 4; ++i) {
        int gi = rowA + ty * 4 + i;
#pragma unroll
        for (int j = 0; j < 4; ++j) {
            int gj = rowB + tx * 4 + j;
            if (gi > gj) {
                float s = acc[i][j] * g_minv[gi] * g_minv[gj];
                unsigned flat = (unsigned)gi * MSZ + (unsigned)gj;
                unsigned long long key =
                    ((unsigned long long)ordf(s) << 32) | (0xFFFFFFFFu - flat);
                if (key > best) best = key;
            }
        }
    }
    __shared__ unsigned long long sred[256];
    sred[tid] = best;
    __syncthreads();
    for (int s = 128; s; s >>= 1) {
        if (tid < s && sred[tid + s] > sred[tid]) sred[tid] = sred[tid + s];
        __syncthreads();
    }
    if (tid == 0) atomicMax(&g_pairmax, sred[0]);
}

// ==== Kernel F: outputs — copy/utilstats -> m_fixup -> mi -> l_fixup ====
__global__ __launch_bounds__(1024) void kF(const float* __restrict__ m,
                                           const float* __restrict__ l,
                                           const float* __restrict__ mu_in,
                                           const float* __restrict__ lu_in,
                                           const int* __restrict__ sptr,
                                           float* __restrict__ out_m,
                                           float* __restrict__ out_l,
                                           float* __restrict__ out_mu,
                                           float* __restrict__ out_lu,
                                           float* __restrict__ out_p) {
    int b = blockIdx.x, t = threadIdx.x;

    if (b == 0) {
        for (int i = t; i < MSZ; i += 1024) out_mu[i] = mu_in[i];
        for (int i = t; i < LSZ; i += 1024) out_lu[i] = lu_in[i];
        float s = 0.f, mv = 1e30f; int mi = 0x7FFFFFFF; int z = 0;
        for (int i = t; i < MSZ; i += 1024) {
            float v = mu_in[i];
            s += v;
            if (v == 0.f) z = 1;
            if (v < mv) { mv = v; mi = i; }
        }
        float tot = blockReduceSum(s);
        if (t == 0) g_mumean = tot / (float)MSZ;
        blockArgBest(mv, mi, 0, nullptr, &g_li);
        __shared__ int sz;
        if (t == 0) sz = 0;
        __syncthreads();
        if (z) atomicOr(&sz, 1);
        __syncthreads();
        if (t == 0) g_isfull = !sz;

        float s2 = 0.f, lv = 1e30f; int lji = 0x7FFFFFFF;
        for (int i = t; i < LSZ; i += 1024) {
            float v = lu_in[i];
            s2 += v;
            if (v < lv) { lv = v; lji = i; }
        }
        float t2 = blockReduceSum(s2);
        if (t == 0) g_lumean = t2 / (float)LSZ;
        blockArgBest(lv, lji, 0, nullptr, &g_lj);
    } else {
        int idx = (b - 1) * 1024 + t;
        int st = (NB - 1) * 1024;
        const int nm = MSZ * DIM / 4, nl = LSZ * DIM / 4;
        for (int k = idx; k < nm; k += st)
            ((float4*)out_m)[k] = ((const float4*)m)[k];
        for (int k = idx; k < nl; k += st)
            ((float4*)out_l)[k] = ((const float4*)l)[k];
    }
    gridbar(NB);

    // p1: m_fixup (block 0); DIM==blockDim so each c-loop is one pass
    if (b == 0) {
        float mumean = g_mumean;
        int li = g_li, msi = g_msi;
        float simcand = g_simcand;
        unsigned long long pk = g_pairmax;
        float isim = iordf((unsigned)(pk >> 32));
        unsigned flat = 0xFFFFFFFFu - (unsigned)(pk & 0xFFFFFFFFu);
        int idx1 = flat / MSZ, idx2 = flat % MSZ;
        __shared__ float ssum;

        if (!g_isfull) {
            out_m[(size_t)li * DIM + t] = g_cand[t];
            if (t == 0) out_mu[li] = mumean + 1e-5f;
        } else if (simcand > 0.98f) {
            float v = (m[(size_t)msi * DIM + t] + g_cand[t]) * 0.5f;
            float tot = blockReduceSum(v * v);
            if (t == 0) ssum = tot;
            __syncthreads();
            float inv = 1.f / fmaxf(sqrtf(ssum), 1e-12f);
            out_m[(size_t)msi * DIM + t] = v * inv;
            if (t == 0) out_mu[msi] = (mu_in[msi] + mumean) * 0.5f;
        } else if (isim > 0.98f) {
            float v = (m[(size_t)idx1 * DIM + t] + m[(size_t)idx2 * DIM + t]) * 0.5f;
            float tot = blockReduceSum(v * v);
            if (t == 0) ssum = tot;
            __syncthreads();
            float inv = 1.f / fmaxf(sqrtf(ssum), 1e-12f);
            out_m[(size_t)idx1 * DIM + t] = v * inv;
            out_m[(size_t)idx2 * DIM + t] = g_cand[t];
            if (t == 0) {
                float old1 = mu_in[idx1];
                float nu1 = (mu_in[idx1] + mu_in[idx2]) * 0.5f;
                out_mu[idx1] = nu1;
                float mean2 = mumean + (nu1 - old1) / (float)MSZ;
                out_mu[idx2] = mean2 + 1e-5f;
            }
        } else {
            if (g_cnsq > g_mnsq[li]) {
                out_m[(size_t)li * DIM + t] = g_cand[t];
                if (t == 0) out_mu[li] = mumean + 1e-5f;
            }
        }
    }
    gridbar(NB);

    // p2: mi = argmax(out_mu) (block 0)
    if (b == 0) {
        float bv = -1e30f; int bi = 0x7FFFFFFF;
        for (int i = t; i < MSZ; i += 1024) {
            float v = out_mu[i];
            if (v > bv) { bv = v; bi = i; }
        }
        blockArgBest(bv, bi, 1, nullptr, &g_mi);
    }
    gridbar(NB);

    // p3: l_fixup (block 0)
    if (b == 0) {
        int lj = g_lj, mi = g_mi;
        out_l[(size_t)lj * DIM + t] =
            0.9f * l[(size_t)lj * DIM + t] + 0.1f * out_m[(size_t)mi * DIM + t];
        if (t == 0) {
            out_lu[lj] = g_lumean;
            out_p[0] = (float)(((*sptr) + KPROM) % SSZ);
        }
    }
}

// ---------------- launch ----------------
extern "C" void kernel_launch(void* const* d_in, const int* in_sizes, int n_in,
                              void* d_out, int out_size) {
    const float* tok = (const float*)d_in[0];
    const float* s_in = (const float*)d_in[1];
    const float* m_in = (const float*)d_in[2];
    const float* l_in = (const float*)d_in[3];
    const float* mu_in = (const float*)d_in[4];
    const float* lu_in = (const float*)d_in[5];
    const float* wq = (const float*)d_in[6];
    const float* bq = (const float*)d_in[7];
    const float* wk = (const float*)d_in[8];
    const int* sptr = (const int*)d_in[10];

    float* out = (float*)d_out;
    float* out_s  = out;
    float* out_m  = out + 524288;
    float* out_l  = out + 4718592;
    float* out_mu = out + 13107200;
    float* out_lu = out + 13111296;
    float* out_p  = out + 13119488;

    // pairmax_i8 stays in slot #4 => ncu verifies the occupancy fix
    kA<<<KA_MNQB + KA_RNB + LPB, 256>>>(m_in, tok, l_in);
    k_topk<<<1, 1024>>>();
    kD<<<NB, 1024>>>(tok, s_in, sptr, wq, bq, wk, m_in, out_s);
    k_pairmax_i8<<<64 * 65 / 2, 256>>>();
    k_pairmax_exact<<<(MSZ / TS) * (MSZ / TS + 1) / 2, 256>>>(m_in);
    kF<<<NB, 1024>>>(m_in, l_in, mu_in, lu_in, sptr,
                     out_m, out_l, out_mu, out_lu, out_p);
}

// round 12
// speedup vs baseline: 1.7683x; 1.7683x over previous
#include <cuda_runtime.h>
#include <math.h>

#define DIM   1024
#define NCAND 16384
#define SSZ   512
#define MSZ   4096
#define LSZ   8192
#define KPROM 128
#define LPB   128
#define NB    148   // fused-kernel grid (<= SM count: co-residency guaranteed)
#define NTILE 528   // 32x33/2 pair tiles (128x128)

// ---------------- device scratch (no allocations allowed) ----------------
__device__ float g_norms[NCAND];
__device__ int   g_topidx[KPROM];
__device__ float g_part[LPB * DIM];
__device__ float g_lmean[DIM];
__device__ float g_q[DIM];
__device__ float g_u[DIM];
__device__ float g_logits[SSZ];
__device__ int   g_best_s;
__device__ float g_cand[DIM];
__device__ float g_cnsq;
__device__ float g_mdot[MSZ];
__device__ float g_mnsq[MSZ];
__device__ float g_minv[MSZ];
__device__ int   g_msi;
__device__ float g_simcand;
__device__ unsigned long long g_pairmax;
__device__ float g_mumean, g_lumean;
__device__ int   g_li, g_lj, g_isfull, g_mi;
__device__ int   g_mi8[MSZ * 256];
__device__ float g_sfac[MSZ];
__device__ float g_tmax64[64 * 64];
__device__ unsigned g_qmax;
__device__ int g_bcnt = 0;
__device__ int g_bgen = 0;
__device__ int g_tile = 0;     // work-stealing counter (reset in kA)

// ---------------- helpers ----------------
__device__ __forceinline__ void gridbar(int nblocks) {
    __syncthreads();
    if (threadIdx.x == 0) {
        volatile int* vgen = &g_bgen;
        int my = *vgen;
        __threadfence();
        int t = atomicAdd(&g_bcnt, 1);
        if (t == nblocks - 1) {
            g_bcnt = 0;
            __threadfence();
            atomicAdd(&g_bgen, 1);
        } else {
            while (*vgen == my) { }
        }
        __threadfence();
    }
    __syncthreads();
}

__device__ __forceinline__ float blockReduceSum(float v) {
    __shared__ float sh[32];
    int lane = threadIdx.x & 31, wid = threadIdx.x >> 5;
    __syncthreads();
#pragma unroll
    for (int o = 16; o; o >>= 1) v += __shfl_down_sync(0xFFFFFFFFu, v, o);
    if (lane == 0) sh[wid] = v;
    __syncthreads();
    int nw = (blockDim.x + 31) >> 5;
    v = (threadIdx.x < nw) ? sh[threadIdx.x] : 0.f;
    if (wid == 0) {
#pragma unroll
        for (int o = 16; o; o >>= 1) v += __shfl_down_sync(0xFFFFFFFFu, v, o);
    }
    return v;  // valid in tid 0
}

__device__ __forceinline__ void blockArgBest(float v, int idx, int maxMode,
                                             float* outv, int* outi) {
    __shared__ float sv[1024];
    __shared__ int   si[1024];
    __syncthreads();
    sv[threadIdx.x] = v; si[threadIdx.x] = idx;
    __syncthreads();
    for (int s = blockDim.x >> 1; s; s >>= 1) {
        if ((int)threadIdx.x < s) {
            float v2 = sv[threadIdx.x + s]; int i2 = si[threadIdx.x + s];
            bool better = maxMode
                ? (v2 > sv[threadIdx.x] || (v2 == sv[threadIdx.x] && i2 < si[threadIdx.x]))
                : (v2 < sv[threadIdx.x] || (v2 == sv[threadIdx.x] && i2 < si[threadIdx.x]));
            if (better) { sv[threadIdx.x] = v2; si[threadIdx.x] = i2; }
        }
        __syncthreads();
    }
    if (threadIdx.x == 0) { if (outv) *outv = sv[0]; *outi = si[0]; }
    __syncthreads();
}

__device__ __forceinline__ unsigned ordf(float f) {
    unsigned u = __float_as_uint(f);
    return (u & 0x80000000u) ? ~u : (u | 0x80000000u);
}
__device__ __forceinline__ float iordf(unsigned u) {
    unsigned b = (u & 0x80000000u) ? (u & 0x7FFFFFFFu) : ~u;
    return __uint_as_float(b);
}

__device__ __forceinline__ float warpRowDot(const float4* __restrict__ a4,
                                            const float4* __restrict__ b4,
                                            int lane) {
    float s = 0.f;
#pragma unroll
    for (int k = 0; k < 8; ++k) {
        float4 a = a4[lane + k * 32];
        float4 b = b4[lane + k * 32];
        s += a.x*b.x + a.y*b.y + a.z*b.z + a.w*b.w;
    }
#pragma unroll
    for (int o = 16; o; o >>= 1) s += __shfl_down_sync(0xFFFFFFFFu, s, o);
    return s;  // valid in lane 0
}

// ===== Kernel A: init + mnq(warp/row) + rownorms(warp/row) + lpart =====
#define KA_MNQB   512
#define KA_RNB    2048
__global__ void kA(const float* __restrict__ m, const float* __restrict__ tok,
                   const float* __restrict__ l) {
    int b = blockIdx.x, t = threadIdx.x;
    int lane = t & 31, w = t >> 5;
    if (b < KA_MNQB) {
        if (b == 0 && t == 0) { g_pairmax = 0ULL; g_qmax = 0u; g_tile = 0; }
        int row = b * 8 + w;
        const float4* p = (const float4*)(m + (size_t)row * DIM);
        float4 va[8];
        float nsq = 0.f, mab = 0.f;
#pragma unroll
        for (int k = 0; k < 8; ++k) {
            float4 v = p[lane + k * 32];
            va[k] = v;
            nsq += v.x*v.x + v.y*v.y + v.z*v.z + v.w*v.w;
            mab = fmaxf(mab, fmaxf(fmaxf(fabsf(v.x), fabsf(v.y)),
                                   fmaxf(fabsf(v.z), fabsf(v.w))));
        }
#pragma unroll
        for (int o = 16; o; o >>= 1) {
            nsq += __shfl_down_sync(0xFFFFFFFFu, nsq, o);
            mab = fmaxf(mab, __shfl_down_sync(0xFFFFFFFFu, mab, o));
        }
        float is;
        if (lane == 0) {
            g_mnsq[row] = nsq;
            float inv = 1.f / fmaxf(sqrtf(nsq), 1e-12f);
            g_minv[row] = inv;
            float scale = (mab > 0.f) ? mab / 127.f : 1.f;
            g_sfac[row] = scale * inv;
            is = (mab > 0.f) ? 127.f / mab : 0.f;
        }
        is = __shfl_sync(0xFFFFFFFFu, is, 0);
#pragma unroll
        for (int k = 0; k < 8; ++k) {
            float4 v = va[k];
            int q0 = max(-127, min(127, __float2int_rn(v.x * is)));
            int q1 = max(-127, min(127, __float2int_rn(v.y * is)));
            int q2 = max(-127, min(127, __float2int_rn(v.z * is)));
            int q3 = max(-127, min(127, __float2int_rn(v.w * is)));
            g_mi8[row * 256 + lane + k * 32] =
                (q0 & 0xFF) | ((q1 & 0xFF) << 8) | ((q2 & 0xFF) << 16) | ((q3 & 0xFF) << 24);
        }
    } else if (b < KA_MNQB + KA_RNB) {
        int row = (b - KA_MNQB) * 8 + w;
        const float4* p = (const float4*)(tok + (size_t)row * DIM);
        float s = 0.f;
#pragma unroll
        for (int k = 0; k < 8; ++k) {
            float4 v = p[lane + k * 32];
            s += v.x*v.x + v.y*v.y + v.z*v.z + v.w*v.w;
        }
#pragma unroll
        for (int o = 16; o; o >>= 1) s += __shfl_down_sync(0xFFFFFFFFu, s, o);
        if (lane == 0) g_norms[row] = s;
    } else {
        int b2 = b - KA_MNQB - KA_RNB;
        float acc[4] = {0.f, 0.f, 0.f, 0.f};
        int r0 = b2 * (LSZ / LPB);
        for (int r = 0; r < LSZ / LPB; ++r) {
            const float* row = l + (size_t)(r0 + r) * DIM;
#pragma unroll
            for (int k = 0; k < 4; ++k) acc[k] += row[t + k * 256];
        }
#pragma unroll
        for (int k = 0; k < 4; ++k) g_part[b2 * DIM + t + k * 256] = acc[k];
    }
}

// ================= Kernel C: fast top-128 =================
__global__ __launch_bounds__(1024) void k_topk() {
    int tid = threadIdx.x, lane = tid & 31, warp = tid >> 5;
    unsigned long long key[16];
#pragma unroll
    for (int i = 0; i < 16; ++i) {
        int idx = tid + i * 1024;
        key[i] = ((unsigned long long)ordf(g_norms[idx]) << 32) |
                 (unsigned long long)(0xFFFFFFFFu - (unsigned)idx);
    }
    unsigned long long lmax = 0ULL;
#pragma unroll
    for (int i = 0; i < 16; ++i) if (key[i] > lmax) lmax = key[i];

    __shared__ unsigned long long wkey[32];
    __shared__ unsigned long long winner;
    for (int it = 0; it < KPROM; ++it) {
        unsigned long long k = lmax;
#pragma unroll
        for (int o = 16; o; o >>= 1) {
            unsigned long long o2 = __shfl_down_sync(0xFFFFFFFFu, k, o);
            if (o2 > k) k = o2;
        }
        if (lane == 0) wkey[warp] = k;
        __syncthreads();
        if (warp == 0) {
            unsigned long long k2 = wkey[lane];
#pragma unroll
            for (int o = 16; o; o >>= 1) {
                unsigned long long o2 = __shfl_down_sync(0xFFFFFFFFu, k2, o);
                if (o2 > k2) k2 = o2;
            }
            if (lane == 0) {
                winner = k2;
                g_topidx[it] = (int)(0xFFFFFFFFu - (unsigned)(k2 & 0xFFFFFFFFu));
            }
        }
        __syncthreads();
        unsigned long long w = winner;
        if (lmax == w) {
            unsigned long long nm = 0ULL;
#pragma unroll
            for (int i = 0; i < 16; ++i) {
                if (key[i] == w) key[i] = 0ULL;
                if (key[i] > nm) nm = key[i];
            }
            lmax = nm;
        }
    }
}

// ==== Kernel D: fused serial chain, 1024 thr/block, warp-per-row dots ====
__global__ __launch_bounds__(1024) void kD(const float* __restrict__ tok,
                                           const float* __restrict__ s_in,
                                           const int* __restrict__ sptr,
                                           const float* __restrict__ wq,
                                           const float* __restrict__ bq,
                                           const float* __restrict__ wk,
                                           const float* __restrict__ m,
                                           float* __restrict__ out_s) {
    int b = blockIdx.x, t = threadIdx.x;
    int lane = t & 31, w = t >> 5;
    int gw = b * 32 + w;

    // p0: build_s + lsum (block 0)
    {
        int sp = *sptr;
        for (int idx = b * 1024 + t; idx < SSZ * 256; idx += NB * 1024) {
            int r = idx >> 8, c = idx & 255;
            int d = ((r - sp) % SSZ + SSZ) % SSZ;
            const float4* src = (d < KPROM)
                ? (const float4*)(tok + (size_t)g_topidx[d] * DIM)
                : (const float4*)(s_in + (size_t)r * DIM);
            ((float4*)(out_s + (size_t)r * DIM))[c] = src[c];
        }
        if (b == 0) {
            float s = 0.f;
            for (int p = 0; p < LPB; ++p) s += g_part[p * DIM + t];
            g_lmean[t] = s * (1.f / (float)LSZ);
        }
    }
    gridbar(NB);

    // p1: q[j]
    if (gw < DIM) {
        float s = warpRowDot((const float4*)(wq + (size_t)gw * DIM),
                             (const float4*)g_lmean, lane);
        if (lane == 0) g_q[gw] = s + bq[gw];
    }
    gridbar(NB);

    // p2: u partials
    if (b < 128) {
        float acc = 0.f;
#pragma unroll
        for (int jj = 0; jj < 8; ++jj) {
            int j = b * 8 + jj;
            acc += wk[(size_t)j * DIM + t] * g_q[j];
        }
        g_part[b * DIM + t] = acc;
    }
    gridbar(NB);

    // p3: usum
    if (b == 0) {
        float s = 0.f;
        for (int p = 0; p < 128; ++p) s += g_part[p * DIM + t];
        g_u[t] = s;
    }
    gridbar(NB);

    // p4: logits
    if (gw < SSZ) {
        float s = warpRowDot((const float4*)(out_s + (size_t)gw * DIM),
                             (const float4*)g_u, lane);
        if (lane == 0) g_logits[gw] = s;
    }
    gridbar(NB);

    // p5: pick
    if (b == 0) {
        float bv = -1e30f; int bi = 0x7FFFFFFF;
        if (t < SSZ) { bv = g_logits[t]; bi = t; }
        blockArgBest(bv, bi, 1, nullptr, &g_best_s);
        int bs = g_best_s;
        float loc = 0.f;
        if (t < 256) {
            float4 v4 = ((const float4*)(out_s + (size_t)bs * DIM))[t];
            ((float4*)g_cand)[t] = v4;
            loc = v4.x*v4.x + v4.y*v4.y + v4.z*v4.z + v4.w*v4.w;
        }
        float tot = blockReduceSum(loc);
        if (t == 0) g_cnsq = tot;
    }
    gridbar(NB);

    // p6: mdots
    if (gw < MSZ) {
        float s = warpRowDot((const float4*)(m + (size_t)gw * DIM),
                             (const float4*)g_cand, lane);
        if (lane == 0) g_mdot[gw] = s;
    }
    gridbar(NB);

    // p7: mstats
    if (b == 0) {
        float cinv = 1.f / fmaxf(sqrtf(g_cnsq), 1e-12f);
        float bv = -1e30f; int bi = 0x7FFFFFFF;
        for (int i = t; i < MSZ; i += 1024) {
            float s = g_mdot[i] * g_minv[i] * cinv;
            if (s > bv) { bv = s; bi = i; }
        }
        blockArgBest(bv, bi, 1, &g_simcand, &g_msi);
    }
}

// == Kernel B: int8 DP4A pair-sim, 128x128 tiles (R8 body), persistent ==
// grid 296 = 2 CTA/SM x 148: single wave; tiles pulled via atomic counter.
// Stealing order nondeterministic, but every output is exactly-once per-tile
// (g_tmax64) or an order-independent packed atomicMax (g_qmax) => deterministic.
#define LDR 36
__global__ __launch_bounds__(256, 2) void k_pairmax_i8() {
    __shared__ int As[128 * LDR];
    __shared__ int Bs[128 * LDR];
    __shared__ float sfA[128], sfB[128];
    __shared__ float wsub[8][2];
    __shared__ int s_tile;

    int tid = threadIdx.x, lane = tid & 31, warp = tid >> 5;
    int tx = tid & 15, ty = tid >> 4;

    while (true) {
        if (tid == 0) s_tile = atomicAdd(&g_tile, 1);
        __syncthreads();
        int b = s_tile;
        if (b >= NTILE) break;

        int bi = (int)((sqrtf(8.f * b + 1.f) - 1.f) * 0.5f);
        while ((bi + 1) * (bi + 2) / 2 <= b) ++bi;
        while (bi * (bi + 1) / 2 > b) --bi;
        int bj = b - bi * (bi + 1) / 2;
        int rowA = bi * 128, rowB = bj * 128;

        if (tid < 128) sfA[tid] = g_sfac[rowA + tid];
        else           sfB[tid - 128] = g_sfac[rowB + tid - 128];

        int acc[8][8];
#pragma unroll
        for (int i = 0; i < 8; ++i)
#pragma unroll
            for (int j = 0; j < 8; ++j) acc[i][j] = 0;

        int ldrow = tid >> 1, ldoff = (tid & 1) * 16;

        for (int c = 0; c < 8; ++c) {
            __syncthreads();
            {
                const int* gA = &g_mi8[(size_t)(rowA + ldrow) * 256 + c * 32 + ldoff];
                const int* gB = &g_mi8[(size_t)(rowB + ldrow) * 256 + c * 32 + ldoff];
                int* sA = &As[ldrow * LDR + ldoff];
                int* sB = &Bs[ldrow * LDR + ldoff];
#pragma unroll
                for (int v = 0; v < 4; ++v) {
                    *(int4*)(sA + v * 4) = *(const int4*)(gA + v * 4);
                    *(int4*)(sB + v * 4) = *(const int4*)(gB + v * 4);
                }
            }
            __syncthreads();
            const int* arow = &As[(ty * 8) * LDR];
            const int* brow = &Bs[tx * LDR];
#pragma unroll
            for (int kq = 0; kq < 8; ++kq) {
#pragma unroll
                for (int jh = 0; jh < 2; ++jh) {
                    int4 b4[4];
#pragma unroll
                    for (int j4 = 0; j4 < 4; ++j4)
                        b4[j4] = *(const int4*)&brow[((jh * 4 + j4) * 16) * LDR + kq * 4];
#pragma unroll
                    for (int i = 0; i < 8; ++i) {
                        int4 a4 = *(const int4*)&arow[i * LDR + kq * 4];
#pragma unroll
                        for (int j4 = 0; j4 < 4; ++j4) {
                            int j = jh * 4 + j4;
                            int s = __dp4a(a4.x, b4[j4].x, acc[i][j]);
                            s = __dp4a(a4.y, b4[j4].y, s);
                            s = __dp4a(a4.z, b4[j4].z, s);
                            acc[i][j] = __dp4a(a4.w, b4[j4].w, s);
                        }
                    }
                }
            }
        }

        float mx[2];
        mx[0] = -1e30f; mx[1] = -1e30f;
#pragma unroll
        for (int i = 0; i < 8; ++i) {
            int gi = rowA + ty * 8 + i;
            float fi = sfA[ty * 8 + i];
#pragma unroll
            for (int j = 0; j < 8; ++j) {
                int cj = tx + 16 * j;
                int gj = rowB + cj;
                if (gi > gj) mx[j >> 2] = fmaxf(mx[j >> 2], (float)acc[i][j] * fi * sfB[cj]);
            }
        }
#pragma unroll
        for (int o = 16; o; o >>= 1) {
            mx[0] = fmaxf(mx[0], __shfl_down_sync(0xFFFFFFFFu, mx[0], o));
            mx[1] = fmaxf(mx[1], __shfl_down_sync(0xFFFFFFFFu, mx[1], o));
        }
        if (lane == 0) { wsub[warp][0] = mx[0]; wsub[warp][1] = mx[1]; }
        __syncthreads();
        if (tid == 0) {
            float g = -1e30f;
            for (int rh = 0; rh < 2; ++rh)
                for (int ch = 0; ch < 2; ++ch) {
                    float m = -1e30f;
                    for (int w2 = rh * 4; w2 < rh * 4 + 4; ++w2)
                        m = fmaxf(m, wsub[w2][ch]);
                    g_tmax64[(2 * bi + rh) * 64 + (2 * bj + ch)] = m;
                    g = fmaxf(g, m);
                }
            atomicMax(&g_qmax, ordf(g));
        }
        __syncthreads();  // wsub/sf reuse + s_tile refetch safety
    }
}

// ==== Kernel E: exact fp32 recompute of candidate tiles ====
#define TS 64
#define KT 16
__global__ __launch_bounds__(256) void k_pairmax_exact(const float* __restrict__ M) {
    int b = blockIdx.x;
    int bi = (int)((sqrtf(8.f * b + 1.f) - 1.f) * 0.5f);
    while ((bi + 1) * (bi + 2) / 2 <= b) ++bi;
    while (bi * (bi + 1) / 2 > b) --bi;
    int bj = b - bi * (bi + 1) / 2;

    float tmax = g_tmax64[bi * 64 + bj];
    float gmax = iordf(g_qmax);
    if (tmax < gmax - 0.025f) return;  // int8 sim error <= 0.011; rigorous margin

    __shared__ float As[TS][KT + 1];
    __shared__ float Bs[TS][KT + 1];
    int tid = threadIdx.x;
    int tx = tid & 15, ty = tid >> 4;
    float acc[4][4];
#pragma unroll
    for (int i = 0; i < 4; ++i)
#pragma unroll
        for (int j = 0; j < 4; ++j) acc[i][j] = 0.f;

    int rowA = bi * TS, rowB = bj * TS;
    int lr = tid >> 2;
    int lc = (tid & 3) * 4;

    for (int k0 = 0; k0 < DIM; k0 += KT) {
        float4 a4 = *(const float4*)&M[(size_t)(rowA + lr) * DIM + k0 + lc];
        float4 b4 = *(const float4*)&M[(size_t)(rowB + lr) * DIM + k0 + lc];
        As[lr][lc] = a4.x; As[lr][lc+1] = a4.y; As[lr][lc+2] = a4.z; As[lr][lc+3] = a4.w;
        Bs[lr][lc] = b4.x; Bs[lr][lc+1] = b4.y; Bs[lr][lc+2] = b4.z; Bs[lr][lc+3] = b4.w;
        __syncthreads();
#pragma unroll
        for (int kk = 0; kk < KT; ++kk) {
            float a[4], bb[4];
#pragma unroll
            for (int i = 0; i < 4; ++i) a[i] = As[ty * 4 + i][kk];
#pragma unroll
            for (int j = 0; j < 4; ++j) bb[j] = Bs[tx * 4 + j][kk];
#pragma unroll
            for (int i = 0; i < 4; ++i)
#pragma unroll
                for (int j = 0; j < 4; ++j) acc[i][j] += a[i] * bb[j];
        }
        __syncthreads();
    }

    unsigned long long best = 0ULL;
#pragma unroll
    for (int i = 0; i < 4; ++i) {
        int gi = rowA + ty * 4 + i;
#pragma unroll
        for (int j = 0; j < 4; ++j) {
            int gj = rowB + tx * 4 + j;
            if (gi > gj) {
                float s = acc[i][j] * g_minv[gi] * g_minv[gj];
                unsigned flat = (unsigned)gi * MSZ + (unsigned)gj;
                unsigned long long key =
                    ((unsigned long long)ordf(s) << 32) | (0xFFFFFFFFu - flat);
                if (key > best) best = key;
            }
        }
    }
    __shared__ unsigned long long sred[256];
    sred[tid] = best;
    __syncthreads();
    for (int s = 128; s; s >>= 1) {
        if (tid < s && sred[tid + s] > sred[tid]) sred[tid] = sred[tid + s];
        __syncthreads();
    }
    if (tid == 0) atomicMax(&g_pairmax, sred[0]);
}

// ==== Kernel F: outputs — copy/utilstats -> m_fixup -> mi -> l_fixup ====
__global__ __launch_bounds__(1024) void kF(const float* __restrict__ m,
                                           const float* __restrict__ l,
                                           const float* __restrict__ mu_in,
                                           const float* __restrict__ lu_in,
                                           const int* __restrict__ sptr,
                                           float* __restrict__ out_m,
                                           float* __restrict__ out_l,
                                           float* __restrict__ out_mu,
                                           float* __restrict__ out_lu,
                                           float* __restrict__ out_p) {
    int b = blockIdx.x, t = threadIdx.x;

    if (b == 0) {
        for (int i = t; i < MSZ; i += 1024) out_mu[i] = mu_in[i];
        for (int i = t; i < LSZ; i += 1024) out_lu[i] = lu_in[i];
        float s = 0.f, mv = 1e30f; int mi = 0x7FFFFFFF; int z = 0;
        for (int i = t; i < MSZ; i += 1024) {
            float v = mu_in[i];
            s += v;
            if (v == 0.f) z = 1;
            if (v < mv) { mv = v; mi = i; }
        }
        float tot = blockReduceSum(s);
        if (t == 0) g_mumean = tot / (float)MSZ;
        blockArgBest(mv, mi, 0, nullptr, &g_li);
        __shared__ int sz;
        if (t == 0) sz = 0;
        __syncthreads();
        if (z) atomicOr(&sz, 1);
        __syncthreads();
        if (t == 0) g_isfull = !sz;

        float s2 = 0.f, lv = 1e30f; int lji = 0x7FFFFFFF;
        for (int i = t; i < LSZ; i += 1024) {
            float v = lu_in[i];
            s2 += v;
            if (v < lv) { lv = v; lji = i; }
        }
        float t2 = blockReduceSum(s2);
        if (t == 0) g_lumean = t2 / (float)LSZ;
        blockArgBest(lv, lji, 0, nullptr, &g_lj);
    } else {
        int idx = (b - 1) * 1024 + t;
        int st = (NB - 1) * 1024;
        const int nm = MSZ * DIM / 4, nl = LSZ * DIM / 4;
        for (int k = idx; k < nm; k += st)
            ((float4*)out_m)[k] = ((const float4*)m)[k];
        for (int k = idx; k < nl; k += st)
            ((float4*)out_l)[k] = ((const float4*)l)[k];
    }
    gridbar(NB);

    // p1: m_fixup (block 0); DIM==blockDim so each c-loop is one pass
    if (b == 0) {
        float mumean = g_mumean;
        int li = g_li, msi = g_msi;
        float simcand = g_simcand;
        unsigned long long pk = g_pairmax;
        float isim = iordf((unsigned)(pk >> 32));
        unsigned flat = 0xFFFFFFFFu - (unsigned)(pk & 0xFFFFFFFFu);
        int idx1 = flat / MSZ, idx2 = flat % MSZ;
        __shared__ float ssum;

        if (!g_isfull) {
            out_m[(size_t)li * DIM + t] = g_cand[t];
            if (t == 0) out_mu[li] = mumean + 1e-5f;
        } else if (simcand > 0.98f) {
            float v = (m[(size_t)msi * DIM + t] + g_cand[t]) * 0.5f;
            float tot = blockReduceSum(v * v);
            if (t == 0) ssum = tot;
            __syncthreads();
            float inv = 1.f / fmaxf(sqrtf(ssum), 1e-12f);
            out_m[(size_t)msi * DIM + t] = v * inv;
            if (t == 0) out_mu[msi] = (mu_in[msi] + mumean) * 0.5f;
        } else if (isim > 0.98f) {
            float v = (m[(size_t)idx1 * DIM + t] + m[(size_t)idx2 * DIM + t]) * 0.5f;
            float tot = blockReduceSum(v * v);
            if (t == 0) ssum = tot;
            __syncthreads();
            float inv = 1.f / fmaxf(sqrtf(ssum), 1e-12f);
            out_m[(size_t)idx1 * DIM + t] = v * inv;
            out_m[(size_t)idx2 * DIM + t] = g_cand[t];
            if (t == 0) {
                float old1 = mu_in[idx1];
                float nu1 = (mu_in[idx1] + mu_in[idx2]) * 0.5f;
                out_mu[idx1] = nu1;
                float mean2 = mumean + (nu1 - old1) / (float)MSZ;
                out_mu[idx2] = mean2 + 1e-5f;
            }
        } else {
            if (g_cnsq > g_mnsq[li]) {
                out_m[(size_t)li * DIM + t] = g_cand[t];
                if (t == 0) out_mu[li] = mumean + 1e-5f;
            }
        }
    }
    gridbar(NB);

    // p2: mi = argmax(out_mu) (block 0)
    if (b == 0) {
        float bv = -1e30f; int bi = 0x7FFFFFFF;
        for (int i = t; i < MSZ; i += 1024) {
            float v = out_mu[i];
            if (v > bv) { bv = v; bi = i; }
        }
        blockArgBest(bv, bi, 1, nullptr, &g_mi);
    }
    gridbar(NB);

    // p3: l_fixup (block 0)
    if (b == 0) {
        int lj = g_lj, mi = g_mi;
        out_l[(size_t)lj * DIM + t] =
            0.9f * l[(size_t)lj * DIM + t] + 0.1f * out_m[(size_t)mi * DIM + t];
        if (t == 0) {
            out_lu[lj] = g_lumean;
            out_p[0] = (float)(((*sptr) + KPROM) % SSZ);
        }
    }
}

// ---------------- launch ----------------
extern "C" void kernel_launch(void* const* d_in, const int* in_sizes, int n_in,
                              void* d_out, int out_size) {
    const float* tok = (const float*)d_in[0];
    const float* s_in = (const float*)d_in[1];
    const float* m_in = (const float*)d_in[2];
    const float* l_in = (const float*)d_in[3];
    const float* mu_in = (const float*)d_in[4];
    const float* lu_in = (const float*)d_in[5];
    const float* wq = (const float*)d_in[6];
    const float* bq = (const float*)d_in[7];
    const float* wk = (const float*)d_in[8];
    const int* sptr = (const int*)d_in[10];

    float* out = (float*)d_out;
    float* out_s  = out;
    float* out_m  = out + 524288;
    float* out_l  = out + 4718592;
    float* out_mu = out + 13107200;
    float* out_lu = out + 13111296;
    float* out_p  = out + 13119488;

    // pairmax_i8 in slot #4 => ncu verifies the persistence win
    kA<<<KA_MNQB + KA_RNB + LPB, 256>>>(m_in, tok, l_in);
    k_topk<<<1, 1024>>>();
    kD<<<NB, 1024>>>(tok, s_in, sptr, wq, bq, wk, m_in, out_s);
    k_pairmax_i8<<<296, 256>>>();
    k_pairmax_exact<<<(MSZ / TS) * (MSZ / TS + 1) / 2, 256>>>(m_in);
    kF<<<NB, 1024>>>(m_in, l_in, mu_in, lu_in, sptr,
                     out_m, out_l, out_mu, out_lu, out_p);
}